// round 11
// baseline (speedup 1.0000x reference)
#include <cuda_runtime.h>
#include <cstdint>

#define TU      204800     // 400 * 512 upsampled length
#define TBLK    400        // frames
#define BATCH   16
#define NH      9          // harmonic_num + 1
#define NROW1   12800      // TU / 16
#define SPT     4          // samples per thread (quarter of a radix-16 row)

// Padded level-1 prefix: [row][0..NROW1], entry 0 = 0, entry R = P[R-1].
__device__ float g_P2[BATCH * NH * (NROW1 + 1)];       // 7.4 MB
// Padded chain checkpoints: [row][t][qi], qi=0 -> 0, qi=1..3 -> s4,s8,s12.
__device__ float g_seq4[BATCH * NH * TBLK * 4];        // 0.9 MB
// Runtime-opaque 1: forces mad.lo -> IMAD (fma pipe) for threefry adds.
__device__ uint32_t g_one = 1;

__device__ __forceinline__ uint32_t madd(uint32_t a, uint32_t b, uint32_t c) {
    uint32_t d;
    asm("mad.lo.s32 %0, %1, %2, %3;" : "=r"(d) : "r"(a), "r"(b), "r"(c));
    return d;
}

// ---------------- threefry2x32, key=(0,42), counter (0,n); bits = x0^x1 ----------------
__device__ __forceinline__ uint32_t noise_bits(uint32_t n, uint32_t one) {
    const uint32_t kK  = 0x1BD11BDAu ^ 42u;
    uint32_t x1 = n + 42u;
    uint32_t x0 = x1;                                   // round 1: x0 was 0
    x1 = __funnelshift_l(x1, x1, 13) ^ x0;
#define TFR(r) { x0 = madd(x1, one, x0); x1 = __funnelshift_l(x1, x1, (r)); x1 ^= x0; }
    TFR(15) TFR(26) TFR(6)
    x0 = madd(one, 42u, x0);      x1 = madd(one, kK + 1u, x1);
    TFR(17) TFR(29) TFR(16) TFR(24)
    x0 = madd(one, kK, x0);       x1 = madd(one, 2u, x1);
    TFR(13) TFR(15) TFR(26) TFR(6)
    /* +ks0 = 0 */                x1 = madd(one, 45u, x1);
    TFR(17) TFR(29) TFR(16) TFR(24)
    x0 = madd(one, 42u, x0);      x1 = madd(one, kK + 4u, x1);
    TFR(13) TFR(15) TFR(26) TFR(6)
    x0 = madd(one, kK, x0);       x1 = madd(one, 5u, x1);
#undef TFR
    return x0 ^ x1;
}

// ---------------- MUFU helpers ----------------
__device__ __forceinline__ float mufu_sin(float r)  { float v; asm("sin.approx.f32 %0, %1;"  : "=f"(v) : "f"(r)); return v; }
__device__ __forceinline__ float mufu_lg2(float t)  { float v; asm("lg2.approx.f32 %0, %1;"  : "=f"(v) : "f"(t)); return v; }
__device__ __forceinline__ float mufu_ex2(float t)  { float v; asm("ex2.approx.f32 %0, %1;"  : "=f"(v) : "f"(t)); return v; }
__device__ __forceinline__ float mufu_rcp(float t)  { float v; asm("rcp.approx.f32 %0, %1;"  : "=f"(v) : "f"(t)); return v; }
__device__ __forceinline__ float mufu_sqrt(float t) { float v; asm("sqrt.approx.f32 %0, %1;" : "=f"(v) : "f"(t)); return v; }

// ---------------- normal/sqrt(2) = erfinv(u) = p*u; truncated Giles, branchless tail ----------------
__device__ __forceinline__ float normal_pu(uint32_t bits) {
    float u2 = __uint_as_float((bits >> 9) | 0x40000000u);     // 2*u01 + 2, exact
    const float lo = -0.99999994039535522461f;
    float u = __fadd_rn(__fadd_rn(u2, -2.0f), lo);
    float t = fmaf(-u, u, 1.0f);                               // 1-u^2 > 0
    float w = __fmul_rn(mufu_lg2(t), -0.6931471805599453f);    // -ln(1-u^2)
    float wc = w - 2.5f;
    float p = -4.39150654e-06f;
    p = fmaf(p, wc, 0.00021858087f);
    p = fmaf(p, wc, -0.00125372503f);
    p = fmaf(p, wc, -0.00417768164f);
    p = fmaf(p, wc, 0.246640727f);
    p = fmaf(p, wc, 1.50140941f);
    float st = mufu_sqrt(w) - 3.0f;
    float pt = fmaf(fmaf(0.00943887047f, st, 1.00167406f), st, 2.83297682f);
    p = (w < 5.0f) ? p : pt;
    return __fmul_rn(p, u);
}

// ---------------- sin(phase), phase = fl(2*pi*C) in [0, ~1.3e5) ----------------
__device__ __forceinline__ float sin_phase(float phase) {
    const float MAGIC = 12582912.0f;                 // 1.5 * 2^23
    float tmp = fmaf(phase, 0.6366197723675814f, MAGIC);
    uint32_t q = __float_as_uint(tmp);               // low bits = round(phase*2/pi)
    float fk = tmp - MAGIC;
    float r = fmaf(fk, -1.5703125f, phase);          // exact
    r = fmaf(fk, -4.8382679489662e-4f, r);           // P2 full precision
    float rr = (q & 1u) ? (1.5707963267948966f - r) : r;
    rr = __uint_as_float(__float_as_uint(rr) ^ ((q & 2u) << 30));
    return mufu_sin(rr);
}

// ---------------- fast tanh ----------------
__device__ __forceinline__ float tanh_fast(float z) {
    float a = fminf(fabsf(z) * 2.8853900817779268f, 64.0f);
    float e = mufu_ex2(a);
    float th = __fmul_rn(e - 1.0f, mufu_rcp(e + 1.0f));
    return copysignf(th, z);
}

// ---------------- Kernel 1: XLA ReduceWindowRewriter radix-16 scan -> g_P2, g_seq4 ----------------
__global__ void scan16_kernel(const float* __restrict__ f0) {
    __shared__ float sm16[TBLK];
    __shared__ float U[TBLK];
    __shared__ float smT1[TBLK * 16];
    __shared__ float inner3[800];
    __shared__ float O2s[800];
    __shared__ float T3[50];
    __shared__ float O3s[50];
    __shared__ float inner4[50];

    const int row = blockIdx.x;                 // 0..143 = b*9+h
    const int b = row / NH, h = row % NH;
    const float m = (float)(h + 1);

    for (int t = threadIdx.x; t < TBLK; t += blockDim.x) {
        float x = __fmul_rn(__fdiv_rn(f0[b * TBLK + t], 48000.0f), m);
        float s = 0.0f;
        g_seq4[(row * TBLK + t) * 4 + 0] = 0.0f;
#pragma unroll
        for (int k = 0; k < 16; k++) {
            s = __fadd_rn(s, x);
            if (k == 3)  g_seq4[(row * TBLK + t) * 4 + 1] = s;
            if (k == 7)  g_seq4[(row * TBLK + t) * 4 + 2] = s;
            if (k == 11) g_seq4[(row * TBLK + t) * 4 + 3] = s;
        }
        sm16[t] = s;
    }
    __syncthreads();

    for (int t = threadIdx.x; t < TBLK; t += blockDim.x) {
        float v = sm16[t], s = 0.0f;
#pragma unroll
        for (int k = 0; k < 16; k++) {
            s = __fadd_rn(s, v);
            smT1[t * 16 + k] = s;
        }
        U[t] = s;
    }
    __syncthreads();

    for (int R3 = threadIdx.x; R3 < 50; R3 += blockDim.x) {
        float s = 0.0f;
        for (int j = 0; j < 16; j++) {
            s = __fadd_rn(s, U[(16 * R3 + j) >> 1]);
            inner3[R3 * 16 + j] = s;
        }
        T3[R3] = s;
    }
    __syncthreads();

    if (threadIdx.x == 0) {
        float T4[4], O4[4];
        for (int r = 0; r < 4; r++) {
            float s = 0.0f;
            for (int j = 0; j < 16; j++) {
                int idx = 16 * r + j;
                float v = (idx < 50) ? T3[idx] : 0.0f;
                s = __fadd_rn(s, v);
                if (idx < 50) inner4[idx] = s;
            }
            T4[r] = s;
        }
        float s = 0.0f;
        for (int r = 0; r < 4; r++) { s = __fadd_rn(s, T4[r]); O4[r] = s; }
        for (int i = 0; i < 50; i++) {
            float e = ((i >> 4) == 0) ? 0.0f : O4[(i >> 4) - 1];
            O3s[i] = __fadd_rn(inner4[i], e);
        }
    }
    __syncthreads();

    for (int i2 = threadIdx.x; i2 < 800; i2 += blockDim.x) {
        float e = ((i2 >> 4) == 0) ? 0.0f : O3s[(i2 >> 4) - 1];
        O2s[i2] = __fadd_rn(inner3[i2], e);
    }
    __syncthreads();

    if (threadIdx.x == 0) g_P2[row * (NROW1 + 1)] = 0.0f;
    for (int R = threadIdx.x; R < NROW1; R += blockDim.x) {
        int t = R >> 5, k = R & 15, R2 = R >> 4;
        float e = (R2 == 0) ? 0.0f : O2s[R2 - 1];
        g_P2[row * (NROW1 + 1) + R + 1] = __fadd_rn(smT1[t * 16 + k], e);
    }
}

// ---------------- Kernel 2: one thread = 4 samples (quarter radix-16 row) ----------------
__global__ void __launch_bounds__(256, 6) nsf_kernel(const float* __restrict__ f0,
                                                     const float* __restrict__ W,
                                                     const float* __restrict__ bias,
                                                     float* __restrict__ out) {
    const int T = blockIdx.x * blockDim.x + threadIdx.x;   // 0 .. BATCH*TU/4-1
    const int b = T / (TU / SPT);
    const int q = T - b * (TU / SPT);                      // quarter-row index in batch
    const int R = q >> 2;                                  // radix-16 row
    const int qi = q & 3;                                  // which quarter
    const int t = R >> 5;
    const int s0 = q << 2;                                 // first sample in batch row

    const uint32_t one = g_one;
    const uint32_t nbase = (uint32_t)(b * TU + s0) * (uint32_t)NH;

    const float f0t = __ldg(&f0[b * TBLK + t]);
    const float rad = __fdiv_rn(f0t, 48000.0f);
    const bool voiced = (f0t > 1.0f);
    const float bias0 = __ldg(&bias[0]);
    const float namp2 = voiced ? 0.0042426406871192851f   // 0.003  * sqrt(2)
                               : 0.047140452079103173f;   // 0.1/3  * sqrt(2)
    const float samp  = voiced ? 0.1f : 0.0f;

    float pre[NH], seqv[NH], wv[NH];
#pragma unroll
    for (int h = 0; h < NH; h++) {
        const int row = b * NH + h;
        pre[h]  = __ldg(&g_P2[row * (NROW1 + 1) + R]);            // padded: no select
        seqv[h] = __ldg(&g_seq4[(row * TBLK + t) * 4 + qi]);      // padded: no select
        wv[h]   = __ldg(&W[h]);
    }

    float4 o;
    float* ov = &o.x;
#pragma unroll
    for (int i = 0; i < SPT; i++) {
        float accS = 0.0f, accN = 0.0f;
        uint32_t n = nbase + (uint32_t)(i * NH);
#pragma unroll
        for (int h = 0; h < NH; h++) {
            const float xh = __fmul_rn(rad, (float)(h + 1));      // fl(rad*m), rematerializable
            seqv[h] = __fadd_rn(seqv[h], xh);                     // continue exact window chain
            const float C = __fadd_rn(seqv[h], pre[h]);
            const float phase = __fmul_rn(C, 6.283185307179586f);
            const float sv = sin_phase(phase);
            const uint32_t bits = noise_bits(n + (uint32_t)h, one);
            const float pu = normal_pu(bits);
            accS = fmaf(sv, wv[h], accS);
            accN = fmaf(pu, wv[h], accN);
        }
        float z = fmaf(accN, namp2, bias0);
        z = fmaf(accS, samp, z);
        ov[i] = tanh_fast(z);
    }
    reinterpret_cast<float4*>(out)[T] = o;                 // coalesced 16B store
}

extern "C" void kernel_launch(void* const* d_in, const int* in_sizes, int n_in,
                              void* d_out, int out_size) {
    const float* f0 = (const float*)d_in[0];
    const float* W;
    const float* bias;
    if (n_in >= 4 && in_sizes[2] == NH)      { W = (const float*)d_in[2]; bias = (const float*)d_in[3]; }
    else if (n_in >= 3 && in_sizes[1] == NH) { W = (const float*)d_in[1]; bias = (const float*)d_in[2]; }
    else                                     { W = (const float*)d_in[2]; bias = (const float*)d_in[3]; }
    float* out = (float*)d_out;

    scan16_kernel<<<BATCH * NH, 256>>>(f0);
    const int nthreads = BATCH * TU / SPT;                 // 819200
    nsf_kernel<<<nthreads / 256, 256>>>(f0, W, bias, out);
}

// round 13
// speedup vs baseline: 1.0414x; 1.0414x over previous
#include <cuda_runtime.h>
#include <cstdint>

#define TU      204800     // 400 * 512 upsampled length
#define TBLK    400        // frames
#define BATCH   16
#define NH      9          // harmonic_num + 1
#define NROW1   12800      // TU / 16
#define SPT     4          // samples per thread (quarter of a radix-16 row)

// Padded level-1 prefix: [row][0..NROW1], entry 0 = 0, entry R = P[R-1].
__device__ float g_P2[BATCH * NH * (NROW1 + 1)];       // 7.4 MB
// Padded chain checkpoints: [row][t][qi], qi=0 -> 0, qi=1..3 -> s4,s8,s12.
__device__ float g_seq4[BATCH * NH * TBLK * 4];        // 0.9 MB
// Runtime-opaque 1: forces mad.lo -> IMAD (fma pipe) for threefry adds.
__device__ uint32_t g_one = 1;

__device__ __forceinline__ uint32_t madd(uint32_t a, uint32_t b, uint32_t c) {
    uint32_t d;
    asm("mad.lo.s32 %0, %1, %2, %3;" : "=r"(d) : "r"(a), "r"(b), "r"(c));
    return d;
}

// ---------------- threefry2x32, key=(0,42), counter (0,n); bits = x0^x1 ----------------
__device__ __forceinline__ uint32_t noise_bits(uint32_t n, uint32_t one) {
    const uint32_t kK  = 0x1BD11BDAu ^ 42u;
    uint32_t x1 = n + 42u;
    uint32_t x0 = x1;                                   // round 1: x0 was 0
    x1 = __funnelshift_l(x1, x1, 13) ^ x0;
#define TFR(r) { x0 = madd(x1, one, x0); x1 = __funnelshift_l(x1, x1, (r)); x1 ^= x0; }
    TFR(15) TFR(26) TFR(6)
    x0 = madd(one, 42u, x0);      x1 = madd(one, kK + 1u, x1);
    TFR(17) TFR(29) TFR(16) TFR(24)
    x0 = madd(one, kK, x0);       x1 = madd(one, 2u, x1);
    TFR(13) TFR(15) TFR(26) TFR(6)
    /* +ks0 = 0 */                x1 = madd(one, 45u, x1);
    TFR(17) TFR(29) TFR(16) TFR(24)
    x0 = madd(one, 42u, x0);      x1 = madd(one, kK + 4u, x1);
    TFR(13) TFR(15) TFR(26) TFR(6)
    x0 = madd(one, kK, x0);       x1 = madd(one, 5u, x1);
#undef TFR
    return x0 ^ x1;
}

// ---------------- MUFU helpers ----------------
__device__ __forceinline__ float mufu_sin(float r)  { float v; asm("sin.approx.f32 %0, %1;"  : "=f"(v) : "f"(r)); return v; }
__device__ __forceinline__ float mufu_lg2(float t)  { float v; asm("lg2.approx.f32 %0, %1;"  : "=f"(v) : "f"(t)); return v; }
__device__ __forceinline__ float mufu_ex2(float t)  { float v; asm("ex2.approx.f32 %0, %1;"  : "=f"(v) : "f"(t)); return v; }
__device__ __forceinline__ float mufu_rcp(float t)  { float v; asm("rcp.approx.f32 %0, %1;"  : "=f"(v) : "f"(t)); return v; }
__device__ __forceinline__ float mufu_sqrt(float t) { float v; asm("sqrt.approx.f32 %0, %1;" : "=f"(v) : "f"(t)); return v; }

// ---------------- normal/sqrt(2) = erfinv(u) = p*u; truncated Giles, branchless tail ----------------
// Two-add form REQUIRED: lo = nextafter(-1,0) guards u > -1 strictly
// (single-sub u2-3 yields u = -1 exactly at bits>>9 == 0 -> lg2(0) = -inf -> poisoned outputs).
__device__ __forceinline__ float normal_pu(uint32_t bits) {
    float u2 = __uint_as_float((bits >> 9) | 0x40000000u);     // 2*u01 + 2, exact
    const float lo = -0.99999994039535522461f;                  // nextafter(-1,0)
    float u = __fadd_rn(__fadd_rn(u2, -2.0f), lo);              // fl(2*u01 + lo) > -1
    float t = fmaf(-u, u, 1.0f);                                // 1-u^2 > 0
    float w = __fmul_rn(mufu_lg2(t), -0.6931471805599453f);     // -ln(1-u^2)
    float wc = w - 2.5f;
    float p = -4.39150654e-06f;
    p = fmaf(p, wc, 0.00021858087f);
    p = fmaf(p, wc, -0.00125372503f);
    p = fmaf(p, wc, -0.00417768164f);
    p = fmaf(p, wc, 0.246640727f);
    p = fmaf(p, wc, 1.50140941f);
    float st = mufu_sqrt(w) - 3.0f;
    float pt = fmaf(fmaf(0.00943887047f, st, 1.00167406f), st, 2.83297682f);
    p = (w < 5.0f) ? p : pt;
    return __fmul_rn(p, u);
}

// ---------------- sin(phase), phase = fl(2*pi*C) in [0, ~1.3e5) ----------------
__device__ __forceinline__ float sin_phase(float phase) {
    const float MAGIC = 12582912.0f;                 // 1.5 * 2^23
    float tmp = fmaf(phase, 0.6366197723675814f, MAGIC);
    uint32_t q = __float_as_uint(tmp);               // low bits = round(phase*2/pi)
    float fk = tmp - MAGIC;
    float r = fmaf(fk, -1.5703125f, phase);          // exact
    r = fmaf(fk, -4.8382679489662e-4f, r);           // P2 full precision
    float rr = (q & 1u) ? (1.5707963267948966f - r) : r;
    rr = __uint_as_float(__float_as_uint(rr) ^ ((q & 2u) << 30));
    return mufu_sin(rr);
}

// ---------------- fast tanh ----------------
__device__ __forceinline__ float tanh_fast(float z) {
    float a = fminf(fabsf(z) * 2.8853900817779268f, 64.0f);
    float e = mufu_ex2(a);
    float th = __fmul_rn(e - 1.0f, mufu_rcp(e + 1.0f));
    return copysignf(th, z);
}

// ---------------- Kernel 1: XLA ReduceWindowRewriter radix-16 scan -> g_P2, g_seq4 ----------------
__global__ void scan16_kernel(const float* __restrict__ f0) {
    __shared__ float sm16[TBLK];
    __shared__ float U[TBLK];
    __shared__ float smT1[TBLK * 16];
    __shared__ float inner3[800];
    __shared__ float O2s[800];
    __shared__ float T3[50];
    __shared__ float O3s[50];
    __shared__ float inner4[50];

    const int row = blockIdx.x;                 // 0..143 = b*9+h
    const int b = row / NH, h = row % NH;
    const float m = (float)(h + 1);

    for (int t = threadIdx.x; t < TBLK; t += blockDim.x) {
        float x = __fmul_rn(__fdiv_rn(f0[b * TBLK + t], 48000.0f), m);
        float s = 0.0f;
        g_seq4[(row * TBLK + t) * 4 + 0] = 0.0f;
#pragma unroll
        for (int k = 0; k < 16; k++) {
            s = __fadd_rn(s, x);
            if (k == 3)  g_seq4[(row * TBLK + t) * 4 + 1] = s;
            if (k == 7)  g_seq4[(row * TBLK + t) * 4 + 2] = s;
            if (k == 11) g_seq4[(row * TBLK + t) * 4 + 3] = s;
        }
        sm16[t] = s;
    }
    __syncthreads();

    for (int t = threadIdx.x; t < TBLK; t += blockDim.x) {
        float v = sm16[t], s = 0.0f;
#pragma unroll
        for (int k = 0; k < 16; k++) {
            s = __fadd_rn(s, v);
            smT1[t * 16 + k] = s;
        }
        U[t] = s;
    }
    __syncthreads();

    for (int R3 = threadIdx.x; R3 < 50; R3 += blockDim.x) {
        float s = 0.0f;
        for (int j = 0; j < 16; j++) {
            s = __fadd_rn(s, U[(16 * R3 + j) >> 1]);
            inner3[R3 * 16 + j] = s;
        }
        T3[R3] = s;
    }
    __syncthreads();

    if (threadIdx.x == 0) {
        float T4[4], O4[4];
        for (int r = 0; r < 4; r++) {
            float s = 0.0f;
            for (int j = 0; j < 16; j++) {
                int idx = 16 * r + j;
                float v = (idx < 50) ? T3[idx] : 0.0f;
                s = __fadd_rn(s, v);
                if (idx < 50) inner4[idx] = s;
            }
            T4[r] = s;
        }
        float s = 0.0f;
        for (int r = 0; r < 4; r++) { s = __fadd_rn(s, T4[r]); O4[r] = s; }
        for (int i = 0; i < 50; i++) {
            float e = ((i >> 4) == 0) ? 0.0f : O4[(i >> 4) - 1];
            O3s[i] = __fadd_rn(inner4[i], e);
        }
    }
    __syncthreads();

    for (int i2 = threadIdx.x; i2 < 800; i2 += blockDim.x) {
        float e = ((i2 >> 4) == 0) ? 0.0f : O3s[(i2 >> 4) - 1];
        O2s[i2] = __fadd_rn(inner3[i2], e);
    }
    __syncthreads();

    if (threadIdx.x == 0) g_P2[row * (NROW1 + 1)] = 0.0f;
    for (int R = threadIdx.x; R < NROW1; R += blockDim.x) {
        int t = R >> 5, k = R & 15, R2 = R >> 4;
        float e = (R2 == 0) ? 0.0f : O2s[R2 - 1];
        g_P2[row * (NROW1 + 1) + R + 1] = __fadd_rn(smT1[t * 16 + k], e);
    }
}

// ---------------- Kernel 2: one thread = 4 samples (quarter radix-16 row) ----------------
__global__ void __launch_bounds__(256) nsf_kernel(const float* __restrict__ f0,
                                                  const float* __restrict__ W,
                                                  const float* __restrict__ bias,
                                                  float* __restrict__ out) {
    const int T = blockIdx.x * blockDim.x + threadIdx.x;   // 0 .. BATCH*TU/4-1
    const int b = T / (TU / SPT);
    const int q = T - b * (TU / SPT);                      // quarter-row index in batch
    const int R = q >> 2;                                  // radix-16 row
    const int qi = q & 3;                                  // which quarter
    const int t = R >> 5;
    const int s0 = q << 2;                                 // first sample in batch row

    const uint32_t one = g_one;
    const uint32_t nbase = (uint32_t)(b * TU + s0) * (uint32_t)NH;

    const float f0t = __ldg(&f0[b * TBLK + t]);
    const float rad = __fdiv_rn(f0t, 48000.0f);
    const bool voiced = (f0t > 1.0f);
    const float bias0 = __ldg(&bias[0]);
    const float namp2 = voiced ? 0.0042426406871192851f   // 0.003  * sqrt(2)
                               : 0.047140452079103173f;   // 0.1/3  * sqrt(2)
    const float samp  = voiced ? 0.1f : 0.0f;

    float xh[NH], pre[NH], seqv[NH], wv[NH];
#pragma unroll
    for (int h = 0; h < NH; h++) {
        const int row = b * NH + h;
        xh[h]   = __fmul_rn(rad, (float)(h + 1));                 // fl(rad*m): matches scan16
        pre[h]  = __ldg(&g_P2[row * (NROW1 + 1) + R]);            // padded: no select
        seqv[h] = __ldg(&g_seq4[(row * TBLK + t) * 4 + qi]);      // padded: no select
        wv[h]   = __ldg(&W[h]);
    }

    float4 o;
    float* ov = &o.x;
#pragma unroll
    for (int i = 0; i < SPT; i++) {
        float accS = 0.0f, accN = 0.0f;
        uint32_t n = nbase + (uint32_t)(i * NH);
#pragma unroll
        for (int h = 0; h < NH; h++) {
            seqv[h] = __fadd_rn(seqv[h], xh[h]);          // continue exact window chain
            const float C = __fadd_rn(seqv[h], pre[h]);
            const float phase = __fmul_rn(C, 6.283185307179586f);
            const float sv = sin_phase(phase);
            const uint32_t bits = noise_bits(n + (uint32_t)h, one);
            const float pu = normal_pu(bits);
            accS = fmaf(sv, wv[h], accS);
            accN = fmaf(pu, wv[h], accN);
        }
        float z = fmaf(accN, namp2, bias0);
        z = fmaf(accS, samp, z);
        ov[i] = tanh_fast(z);
    }
    reinterpret_cast<float4*>(out)[T] = o;                 // coalesced 16B store
}

extern "C" void kernel_launch(void* const* d_in, const int* in_sizes, int n_in,
                              void* d_out, int out_size) {
    const float* f0 = (const float*)d_in[0];
    const float* W;
    const float* bias;
    if (n_in >= 4 && in_sizes[2] == NH)      { W = (const float*)d_in[2]; bias = (const float*)d_in[3]; }
    else if (n_in >= 3 && in_sizes[1] == NH) { W = (const float*)d_in[1]; bias = (const float*)d_in[2]; }
    else                                     { W = (const float*)d_in[2]; bias = (const float*)d_in[3]; }
    float* out = (float*)d_out;

    scan16_kernel<<<BATCH * NH, 256>>>(f0);
    const int nthreads = BATCH * TU / SPT;                 // 819200
    nsf_kernel<<<nthreads / 256, 256>>>(f0, W, bias, out);
}

// round 14
// speedup vs baseline: 1.0969x; 1.0533x over previous
#include <cuda_runtime.h>
#include <cstdint>

#define TU      204800     // 400 * 512 upsampled length
#define TBLK    400        // frames
#define BATCH   16
#define NH      9          // harmonic_num + 1
#define NROW1   12800      // TU / 16
#define SPT     4          // samples per thread (quarter of a radix-16 row)

// Padded level-1 prefix: [row][0..NROW1], entry 0 = 0, entry R = P[R-1].
__device__ float g_P2[BATCH * NH * (NROW1 + 1)];       // 7.4 MB
// Padded chain checkpoints: [row][t][qi], qi=0 -> 0, qi=1..3 -> s4,s8,s12.
__device__ float g_seq4[BATCH * NH * TBLK * 4];        // 0.9 MB
// Runtime-opaque 1: forces mad.lo -> IMAD (fma pipe) for threefry adds.
__device__ uint32_t g_one = 1;

__device__ __forceinline__ uint32_t madd(uint32_t a, uint32_t b, uint32_t c) {
    uint32_t d;
    asm("mad.lo.s32 %0, %1, %2, %3;" : "=r"(d) : "r"(a), "r"(b), "r"(c));
    return d;
}

// ---------------- threefry2x32, key=(0,42), counter (0,n); bits = x0^x1 ----------------
__device__ __forceinline__ uint32_t noise_bits(uint32_t n, uint32_t one) {
    const uint32_t kK  = 0x1BD11BDAu ^ 42u;
    uint32_t x1 = n + 42u;
    uint32_t x0 = x1;                                   // round 1: x0 was 0
    x1 = __funnelshift_l(x1, x1, 13) ^ x0;
#define TFR(r) { x0 = madd(x1, one, x0); x1 = __funnelshift_l(x1, x1, (r)); x1 ^= x0; }
    TFR(15) TFR(26) TFR(6)
    x0 = madd(one, 42u, x0);      x1 = madd(one, kK + 1u, x1);
    TFR(17) TFR(29) TFR(16) TFR(24)
    x0 = madd(one, kK, x0);       x1 = madd(one, 2u, x1);
    TFR(13) TFR(15) TFR(26) TFR(6)
    /* +ks0 = 0 */                x1 = madd(one, 45u, x1);
    TFR(17) TFR(29) TFR(16) TFR(24)
    x0 = madd(one, 42u, x0);      x1 = madd(one, kK + 4u, x1);
    TFR(13) TFR(15) TFR(26) TFR(6)
    x0 = madd(one, kK, x0);       x1 = madd(one, 5u, x1);
#undef TFR
    return x0 ^ x1;
}

// ---------------- MUFU helpers ----------------
__device__ __forceinline__ float mufu_sin(float r)  { float v; asm("sin.approx.f32 %0, %1;"  : "=f"(v) : "f"(r)); return v; }
__device__ __forceinline__ float mufu_lg2(float t)  { float v; asm("lg2.approx.f32 %0, %1;"  : "=f"(v) : "f"(t)); return v; }
__device__ __forceinline__ float mufu_ex2(float t)  { float v; asm("ex2.approx.f32 %0, %1;"  : "=f"(v) : "f"(t)); return v; }
__device__ __forceinline__ float mufu_rcp(float t)  { float v; asm("rcp.approx.f32 %0, %1;"  : "=f"(v) : "f"(t)); return v; }
__device__ __forceinline__ float mufu_sqrt(float t) { float v; asm("sqrt.approx.f32 %0, %1;" : "=f"(v) : "f"(t)); return v; }

// ---------------- normal/sqrt(2) = erfinv(u) = p*u; truncated Giles, branchless tail ----------------
// Two-add form REQUIRED: lo = nextafter(-1,0) guards u > -1 strictly
// (single-sub u2-3 yields u = -1 exactly at bits>>9 == 0 -> lg2(0) = -inf -> poisoned outputs).
__device__ __forceinline__ float normal_pu(uint32_t bits) {
    float u2 = __uint_as_float((bits >> 9) | 0x40000000u);     // 2*u01 + 2, exact
    const float lo = -0.99999994039535522461f;                  // nextafter(-1,0)
    float u = __fadd_rn(__fadd_rn(u2, -2.0f), lo);              // fl(2*u01 + lo) > -1
    float t = fmaf(-u, u, 1.0f);                                // 1-u^2 > 0
    float w = __fmul_rn(mufu_lg2(t), -0.6931471805599453f);     // -ln(1-u^2)
    float wc = w - 2.5f;
    float p = -4.39150654e-06f;
    p = fmaf(p, wc, 0.00021858087f);
    p = fmaf(p, wc, -0.00125372503f);
    p = fmaf(p, wc, -0.00417768164f);
    p = fmaf(p, wc, 0.246640727f);
    p = fmaf(p, wc, 1.50140941f);
    float st = mufu_sqrt(w) - 3.0f;
    float pt = fmaf(fmaf(0.00943887047f, st, 1.00167406f), st, 2.83297682f);
    p = (w < 5.0f) ? p : pt;
    return __fmul_rn(p, u);
}

// ---------------- sin(phase), phase = fl(2*pi*C) in [0, ~1.3e5): mod-2pi reduction ----------------
// fk = round(phase/2pi) exact via magic (fk < 2^14). P1 = 6.28125 (9 mantissa bits)
// => fk*P1 exact and the subtraction cancels exactly; P2 = 2pi - P1 (f32).
// Residual r in [-pi, pi] where MUFU.SIN is spec-accurate (~2^-21 abs).
// Total arg error <= ~3e-6 rad. No quadrant logic, no selects, zero alu ops.
__device__ __forceinline__ float sin_phase(float phase) {
    const float MAGIC = 12582912.0f;                   // 1.5 * 2^23
    const float INV2PI = 0.15915494309189535f;
    const float P1 = 6.28125f;                         // 2pi head, 9 mantissa bits
    const float P2 = 1.9353071795864769e-3f;           // 2pi - P1
    float tmp = fmaf(phase, INV2PI, MAGIC);
    float fk = tmp - MAGIC;                            // exact round-to-nearest integer
    float r = fmaf(fk, -P1, phase);                    // exact
    r = fmaf(fk, -P2, r);                              // one rounding
    return mufu_sin(r);
}

// ---------------- fast tanh ----------------
__device__ __forceinline__ float tanh_fast(float z) {
    float a = fminf(fabsf(z) * 2.8853900817779268f, 64.0f);
    float e = mufu_ex2(a);
    float th = __fmul_rn(e - 1.0f, mufu_rcp(e + 1.0f));
    return copysignf(th, z);
}

// ---------------- Kernel 1: XLA ReduceWindowRewriter radix-16 scan -> g_P2, g_seq4 ----------------
__global__ void scan16_kernel(const float* __restrict__ f0) {
    __shared__ float sm16[TBLK];
    __shared__ float U[TBLK];
    __shared__ float smT1[TBLK * 16];
    __shared__ float inner3[800];
    __shared__ float O2s[800];
    __shared__ float T3[50];
    __shared__ float O3s[50];
    __shared__ float inner4[50];

    const int row = blockIdx.x;                 // 0..143 = b*9+h
    const int b = row / NH, h = row % NH;
    const float m = (float)(h + 1);

    for (int t = threadIdx.x; t < TBLK; t += blockDim.x) {
        float x = __fmul_rn(__fdiv_rn(f0[b * TBLK + t], 48000.0f), m);
        float s = 0.0f;
        g_seq4[(row * TBLK + t) * 4 + 0] = 0.0f;
#pragma unroll
        for (int k = 0; k < 16; k++) {
            s = __fadd_rn(s, x);
            if (k == 3)  g_seq4[(row * TBLK + t) * 4 + 1] = s;
            if (k == 7)  g_seq4[(row * TBLK + t) * 4 + 2] = s;
            if (k == 11) g_seq4[(row * TBLK + t) * 4 + 3] = s;
        }
        sm16[t] = s;
    }
    __syncthreads();

    for (int t = threadIdx.x; t < TBLK; t += blockDim.x) {
        float v = sm16[t], s = 0.0f;
#pragma unroll
        for (int k = 0; k < 16; k++) {
            s = __fadd_rn(s, v);
            smT1[t * 16 + k] = s;
        }
        U[t] = s;
    }
    __syncthreads();

    for (int R3 = threadIdx.x; R3 < 50; R3 += blockDim.x) {
        float s = 0.0f;
        for (int j = 0; j < 16; j++) {
            s = __fadd_rn(s, U[(16 * R3 + j) >> 1]);
            inner3[R3 * 16 + j] = s;
        }
        T3[R3] = s;
    }
    __syncthreads();

    if (threadIdx.x == 0) {
        float T4[4], O4[4];
        for (int r = 0; r < 4; r++) {
            float s = 0.0f;
            for (int j = 0; j < 16; j++) {
                int idx = 16 * r + j;
                float v = (idx < 50) ? T3[idx] : 0.0f;
                s = __fadd_rn(s, v);
                if (idx < 50) inner4[idx] = s;
            }
            T4[r] = s;
        }
        float s = 0.0f;
        for (int r = 0; r < 4; r++) { s = __fadd_rn(s, T4[r]); O4[r] = s; }
        for (int i = 0; i < 50; i++) {
            float e = ((i >> 4) == 0) ? 0.0f : O4[(i >> 4) - 1];
            O3s[i] = __fadd_rn(inner4[i], e);
        }
    }
    __syncthreads();

    for (int i2 = threadIdx.x; i2 < 800; i2 += blockDim.x) {
        float e = ((i2 >> 4) == 0) ? 0.0f : O3s[(i2 >> 4) - 1];
        O2s[i2] = __fadd_rn(inner3[i2], e);
    }
    __syncthreads();

    if (threadIdx.x == 0) g_P2[row * (NROW1 + 1)] = 0.0f;
    for (int R = threadIdx.x; R < NROW1; R += blockDim.x) {
        int t = R >> 5, k = R & 15, R2 = R >> 4;
        float e = (R2 == 0) ? 0.0f : O2s[R2 - 1];
        g_P2[row * (NROW1 + 1) + R + 1] = __fadd_rn(smT1[t * 16 + k], e);
    }
}

// ---------------- Kernel 2: one thread = 4 samples (quarter radix-16 row) ----------------
__global__ void __launch_bounds__(256) nsf_kernel(const float* __restrict__ f0,
                                                  const float* __restrict__ W,
                                                  const float* __restrict__ bias,
                                                  float* __restrict__ out) {
    const int T = blockIdx.x * blockDim.x + threadIdx.x;   // 0 .. BATCH*TU/4-1
    const int b = T / (TU / SPT);
    const int q = T - b * (TU / SPT);                      // quarter-row index in batch
    const int R = q >> 2;                                  // radix-16 row
    const int qi = q & 3;                                  // which quarter
    const int t = R >> 5;
    const int s0 = q << 2;                                 // first sample in batch row

    const uint32_t one = g_one;
    const uint32_t nbase = (uint32_t)(b * TU + s0) * (uint32_t)NH;

    const float f0t = __ldg(&f0[b * TBLK + t]);
    const float rad = __fdiv_rn(f0t, 48000.0f);
    const bool voiced = (f0t > 1.0f);
    const float bias0 = __ldg(&bias[0]);
    const float namp2 = voiced ? 0.0042426406871192851f   // 0.003  * sqrt(2)
                               : 0.047140452079103173f;   // 0.1/3  * sqrt(2)
    const float samp  = voiced ? 0.1f : 0.0f;

    float xh[NH], pre[NH], seqv[NH], wv[NH];
#pragma unroll
    for (int h = 0; h < NH; h++) {
        const int row = b * NH + h;
        xh[h]   = __fmul_rn(rad, (float)(h + 1));                 // fl(rad*m): matches scan16
        pre[h]  = __ldg(&g_P2[row * (NROW1 + 1) + R]);            // padded: no select
        seqv[h] = __ldg(&g_seq4[(row * TBLK + t) * 4 + qi]);      // padded: no select
        wv[h]   = __ldg(&W[h]);
    }

    float4 o;
    float* ov = &o.x;
#pragma unroll
    for (int i = 0; i < SPT; i++) {
        float accS = 0.0f, accN = 0.0f;
        uint32_t n = nbase + (uint32_t)(i * NH);
#pragma unroll
        for (int h = 0; h < NH; h++) {
            seqv[h] = __fadd_rn(seqv[h], xh[h]);          // continue exact window chain
            const float C = __fadd_rn(seqv[h], pre[h]);
            const float phase = __fmul_rn(C, 6.283185307179586f);
            const float sv = sin_phase(phase);
            const uint32_t bits = noise_bits(n + (uint32_t)h, one);
            const float pu = normal_pu(bits);
            accS = fmaf(sv, wv[h], accS);
            accN = fmaf(pu, wv[h], accN);
        }
        float z = fmaf(accN, namp2, bias0);
        z = fmaf(accS, samp, z);
        ov[i] = tanh_fast(z);
    }
    reinterpret_cast<float4*>(out)[T] = o;                 // coalesced 16B store
}

extern "C" void kernel_launch(void* const* d_in, const int* in_sizes, int n_in,
                              void* d_out, int out_size) {
    const float* f0 = (const float*)d_in[0];
    const float* W;
    const float* bias;
    if (n_in >= 4 && in_sizes[2] == NH)      { W = (const float*)d_in[2]; bias = (const float*)d_in[3]; }
    else if (n_in >= 3 && in_sizes[1] == NH) { W = (const float*)d_in[1]; bias = (const float*)d_in[2]; }
    else                                     { W = (const float*)d_in[2]; bias = (const float*)d_in[3]; }
    float* out = (float*)d_out;

    scan16_kernel<<<BATCH * NH, 256>>>(f0);
    const int nthreads = BATCH * TU / SPT;                 // 819200
    nsf_kernel<<<nthreads / 256, 256>>>(f0, W, bias, out);
}